// round 16
// baseline (speedup 1.0000x reference)
#include <cuda_runtime.h>
#include <cuda_bf16.h>
#include <cstdint>
#include <cstddef>

namespace {
constexpr int Bn=64,Sn=512,Hn=1024,On=512;
constexpr int NG=128,NB=144,NTH=512;
constexpr int ABUF=17408;              // 64 rows * 272B
constexpr int WBUF=8704;               // 32 rows * 272B
constexpr int BUF=2*ABUF+2*WBUF;       // 52224
constexpr int NSTG=4;
constexpr int PLOFF=NSTG*BUF;          // 208896
constexpr int SBYO=PLOFF+64*34*4;      // 217600
constexpr int SMEMSZ=SBYO+128;         // 217728
}

__device__ __align__(16) __nv_bfloat16 g_Wg_hi[6291456];   // 128*12*32*128
__device__ __align__(16) __nv_bfloat16 g_Wg_lo[6291456];
__device__ __align__(16) __nv_bfloat16 g_Wy_hi[524288];    // 16*8*32*128
__device__ __align__(16) __nv_bfloat16 g_Wy_lo[524288];
__device__ __align__(16) __nv_bfloat16 g_xA_hi[16777216];  // 512*4*64*128
__device__ __align__(16) __nv_bfloat16 g_xA_lo[16777216];
__device__ __align__(16) __nv_bfloat16 g_hA_hi[131072];    // 2*8*64*128
__device__ __align__(16) __nv_bfloat16 g_hA_lo[131072];
__device__ unsigned g_count=0;
__device__ volatile unsigned g_gen=0;

static __device__ __forceinline__ void cp16(unsigned dst,const void* src){
    asm volatile("cp.async.cg.shared.global [%0], [%1], 16;"::"r"(dst),"l"(src));}
static __device__ __forceinline__ void cp_commit(){
    asm volatile("cp.async.commit_group;":::"memory");}
template<int N> static __device__ __forceinline__ void cp_wait(){
    asm volatile("cp.async.wait_group %0;"::"n"(N):"memory");}
static __device__ __forceinline__ void bar64(int id){
    asm volatile("bar.sync %0, 64;"::"r"(id):"memory");}
static __device__ __forceinline__ void red_sh(unsigned ad,float v){
    asm volatile("red.shared.add.f32 [%0], %1;"::"r"(ad),"f"(v):"memory");}

#define LDM4(r0,r1,r2,r3,addr) \
    asm volatile("ldmatrix.sync.aligned.m8n8.x4.shared.b16 {%0,%1,%2,%3}, [%4];" \
        : "=r"(r0),"=r"(r1),"=r"(r2),"=r"(r3) : "r"(addr))

#define MMA(d,a0,a1,a2,a3,b0,b1) \
    asm volatile("mma.sync.aligned.m16n8k16.row.col.f32.bf16.bf16.f32 " \
        "{%0,%1,%2,%3},{%4,%5,%6,%7},{%8,%9},{%0,%1,%2,%3};" \
        : "+f"((d)[0]),"+f"((d)[1]),"+f"((d)[2]),"+f"((d)[3]) \
        : "r"(a0),"r"(a1),"r"(a2),"r"(a3),"r"(b0),"r"(b1))

static __device__ __forceinline__ float sigm(float v){return 1.0f/(1.0f+__expf(-v));}

static __device__ __forceinline__ void grid_barrier(){
    __syncthreads();
    if(threadIdx.x==0){
        __threadfence();
        unsigned my=g_gen;
        if(atomicAdd(&g_count,1u)==(unsigned)(NB-1)){g_count=0u;__threadfence();g_gen=my+1u;}
        else{while(g_gen==my){} __threadfence();}
    }
    __syncthreads();
}

// ---- prologue: fp32 -> bf16 hi/lo chunk layouts (row-major 128-el rows) ----
__global__ void prep_kernel(const float* __restrict__ Wf,const float* __restrict__ Wi,
                            const float* __restrict__ Wc,const float* __restrict__ Wo,
                            const float* __restrict__ Wy,const float* __restrict__ x,
                            const float* __restrict__ h0){
    const long long NWg=4LL*1024*1536, NWy=512LL*1024, Nx=64LL*512*512, Nh=64LL*1024;
    const long long TOT=NWg+NWy+Nx+Nh;
    for(long long idx=(long long)blockIdx.x*blockDim.x+threadIdx.x; idx<TOT;
        idx+=(long long)gridDim.x*blockDim.x){
        float v; long long d; __nv_bfloat16 *hi,*lo;
        if(idx<NWg){
            int g=(int)(idx/(1024*1536)); int r2=(int)(idx%(1024*1536));
            int n=r2/1536,k=r2%1536;
            const float* W=(g==0)?Wf:(g==1)?Wi:(g==2)?Wc:Wo;
            v=W[(size_t)n*1536+k];
            int blk=n>>3, rr=g*8+(n&7), ch=k>>7, kk=k&127;
            d=(((long long)blk*12+ch)*32+rr)*128+kk; hi=g_Wg_hi; lo=g_Wg_lo;
        }else if(idx<NWg+NWy){
            int i2=(int)(idx-NWg); int o=i2/1024,k=i2%1024;
            v=Wy[(size_t)o*1024+k];
            int cy=o>>5, rr=o&31, ch=k>>7, kk=k&127;
            d=(((long long)cy*8+ch)*32+rr)*128+kk; hi=g_Wy_hi; lo=g_Wy_lo;
        }else if(idx<NWg+NWy+Nx){
            long long i2=idx-NWg-NWy;
            int r=(int)(i2/(512*512)),s=(int)((i2/512)%512),k=(int)(i2%512);
            v=x[i2];
            int ch=k>>7, kk=k&127;
            d=(((long long)s*4+ch)*64+r)*128+kk; hi=g_xA_hi; lo=g_xA_lo;
        }else{
            int i2=(int)(idx-NWg-NWy-Nx); int r=i2>>10,n=i2&1023;
            v=h0[i2];
            int ch=n>>7, kk=n&127;
            d=((long long)ch*64+r)*128+kk; hi=g_hA_hi; lo=g_hA_lo;   // phase 0
        }
        __nv_bfloat16 bh=__float2bfloat16_rn(v);
        hi[d]=bh; lo[d]=__float2bfloat16_rn(v-__bfloat162float(bh));
    }
}

// ---- persistent tensor-core LSTM: per-warp pipelines, pair barriers ----
__global__ void __launch_bounds__(NTH,1) lstm_mma(
    const float* __restrict__ c0,
    const float* __restrict__ bf_,const float* __restrict__ bi_,
    const float* __restrict__ bc_,const float* __restrict__ bo_,
    const float* __restrict__ by_,float* __restrict__ out){
    extern __shared__ char smem[];
    const unsigned sb=(unsigned)__cvta_generic_to_shared(smem);
    const int blk=blockIdx.x,t=threadIdx.x,wrp=t>>5,lane=t&31;
    float* yout=out;
    float* hout=out+(size_t)Bn*Sn*On;
    float* cout=hout+(size_t)Bn*Hn;
    float* plane=(float*)(smem+PLOFF);

    const int wm=wrp&1, wk=wrp>>1;          // M-half, k-slice
    const unsigned kofs=wk*32;              // bytes
    const int ke=wk*16;                     // elems
    const int arow=lane&15, aseg=(lane>>4)*16;
    const int brow=((lane>>4)<<3)+(lane&7), bofs=((lane>>3)&1)*16;

    float acc[2][4][4];

    // zero reduction plane
    for(int o=t;o<64*34;o+=NTH) plane[o]=0.0f;
    __syncthreads();

    auto compute=[&](int c){
        unsigned Ab=sb+(unsigned)(c&3)*BUF, Wb=Ab+2*ABUF;
        unsigned bh[8],bl[8];
        unsigned b0=Wb+brow*272+kofs+bofs;
        LDM4(bh[0],bh[1],bh[2],bh[3],b0);
        LDM4(bh[4],bh[5],bh[6],bh[7],b0+16*272);
        LDM4(bl[0],bl[1],bl[2],bl[3],b0+WBUF);
        LDM4(bl[4],bl[5],bl[6],bl[7],b0+WBUF+16*272);
        unsigned a0=Ab+(wm*32+arow)*272+kofs+aseg;
#pragma unroll
        for(int m=0;m<2;++m){
            unsigned ah0,ah1,ah2,ah3,al0,al1,al2,al3;
            LDM4(ah0,ah1,ah2,ah3,a0+m*4352);
            LDM4(al0,al1,al2,al3,a0+m*4352+ABUF);
#pragma unroll
            for(int n=0;n<4;++n){
                MMA(acc[m][n],ah0,ah1,ah2,ah3,bh[2*n],bh[2*n+1]);
                MMA(acc[m][n],al0,al1,al2,al3,bh[2*n],bh[2*n+1]);
                MMA(acc[m][n],ah0,ah1,ah2,ah3,bl[2*n],bl[2*n+1]);
            }
        }
    };
    auto do_red=[&](){
        int g=lane>>2,t2=lane&3;
#pragma unroll
        for(int m=0;m<2;++m)
#pragma unroll
            for(int q=0;q<4;++q){
                int r=wm*32+16*m+8*(q>>1)+g;
                unsigned rowad=(unsigned)__cvta_generic_to_shared(&plane[r*34+2*t2+(q&1)]);
#pragma unroll
                for(int n=0;n<4;++n) red_sh(rowad+n*32,acc[m][n][q]);
            }
    };

    if(blk<NG){
        const int n0=blk*8;
        float cell[8],vbf[8],vbi[8],vbc[8],vbo[8];
        if(t<64){
#pragma unroll
            for(int d=0;d<8;++d){
                cell[d]=c0[(size_t)t*Hn+n0+d];
                vbf[d]=bf_[n0+d];vbi[d]=bi_[n0+d];vbc[d]=bc_[n0+d];vbo[d]=bo_[n0+d];
            }
        }
        // per-warp slice staging: A (own), W (wm==0, pair-shared)
        auto stage=[&](int it2,int c,int b){
            const __nv_bfloat16 *ah,*al;
            if(c<4){ size_t o=((size_t)it2*4+c)*8192; ah=g_xA_hi+o; al=g_xA_lo+o; }
            else   { size_t o=((size_t)(it2&1)*8+(c-4))*8192; ah=g_hA_hi+o; al=g_hA_lo+o; }
            unsigned base=sb+(unsigned)b*BUF;
#pragma unroll
            for(int j=0;j<4;++j){
                int u=lane+32*j; int hb=u>>6,r=(u>>1)&31,s=u&1;
                unsigned dst=base+hb*ABUF+(wm*32+r)*272+kofs+s*16;
                const __nv_bfloat16* src=(hb?al:ah)+(size_t)(wm*32+r)*128+ke+s*8;
                cp16(dst,src);
            }
            if(wm==0){
                size_t wo=((size_t)blk*12+c)*4096;
                const __nv_bfloat16* wh=g_Wg_hi+wo; const __nv_bfloat16* wl=g_Wg_lo+wo;
#pragma unroll
                for(int j=0;j<4;++j){
                    int u=lane+32*j; int hb=u>>6,r=(u>>1)&31,s=u&1;
                    unsigned dst=base+2*ABUF+hb*WBUF+r*272+kofs+s*16;
                    const __nv_bfloat16* src=(hb?wl:wh)+(size_t)r*128+ke+s*8;
                    cp16(dst,src);
                }
            }
        };

        stage(0,0,0); cp_commit();
        stage(0,1,1); cp_commit();
        stage(0,2,2); cp_commit();
#pragma unroll 1
        for(int it=0;it<Sn;++it){
#pragma unroll
            for(int m=0;m<2;++m)
#pragma unroll
                for(int n=0;n<4;++n)
#pragma unroll
                    for(int q=0;q<4;++q) acc[m][n][q]=0.0f;
#pragma unroll 1
            for(int c=0;c<12;++c){
                cp_wait<2>();
                bar64(1+wk);                  // pair: W visible + WAR cleared
                int nc=c+3;
                if(nc<12) stage(it,nc,nc&3);
                else if(it+1<Sn) stage(it+1,nc-12,nc&3);   // next-step x prefetch
                cp_commit();
                compute(c);
            }
            do_red();
            __syncthreads();
            if(t<64){
                float P[32];
#pragma unroll
                for(int c2=0;c2<32;++c2) P[c2]=plane[t*34+c2];
                unsigned short hs[8],ls[8];
#pragma unroll
                for(int d=0;d<8;++d){
                    float f=sigm(P[d]+vbf[d]);
                    float ii=sigm(P[8+d]+vbi[d]);
                    float g=tanhf(P[16+d]+vbc[d]);
                    float o=sigm(P[24+d]+vbo[d]);
                    cell[d]=f*cell[d]+ii*g;
                    float hh=o*tanhf(cell[d]);
                    __nv_bfloat16 bh2=__float2bfloat16_rn(hh);
                    __nv_bfloat16 bl2=__float2bfloat16_rn(hh-__bfloat162float(bh2));
                    hs[d]=__bfloat16_as_ushort(bh2); ls[d]=__bfloat16_as_ushort(bl2);
                    if(it==Sn-1){ hout[(size_t)t*Hn+n0+d]=hh; cout[(size_t)t*Hn+n0+d]=cell[d]; }
                }
                int p1=(it+1)&1,hc=n0>>7,ko=n0&127;
                size_t eo=(((size_t)p1*8+hc)*64+t)*128+ko;
                uint4 vh=make_uint4(hs[0]|((unsigned)hs[1]<<16),hs[2]|((unsigned)hs[3]<<16),
                                    hs[4]|((unsigned)hs[5]<<16),hs[6]|((unsigned)hs[7]<<16));
                uint4 vl=make_uint4(ls[0]|((unsigned)ls[1]<<16),ls[2]|((unsigned)ls[3]<<16),
                                    ls[4]|((unsigned)ls[5]<<16),ls[6]|((unsigned)ls[7]<<16));
                *(uint4*)((char*)g_hA_hi+eo*2)=vh;
                *(uint4*)((char*)g_hA_lo+eo*2)=vl;
            }
            __syncthreads();
            for(int o=t;o<64*34;o+=NTH) plane[o]=0.0f;   // re-zero for next step
            grid_barrier();
        }
    }else{
        const int cyj=blk-NG, cy0=cyj*32;
        float* sby=(float*)(smem+SBYO);
        if(t<32) sby[t]=by_[cy0+t];
        __syncthreads();
        auto stage=[&](int p,int c,int b){
            size_t o=((size_t)p*8+c)*8192;
            const __nv_bfloat16* ah=g_hA_hi+o; const __nv_bfloat16* al=g_hA_lo+o;
            unsigned base=sb+(unsigned)b*BUF;
#pragma unroll
            for(int j=0;j<4;++j){
                int u=lane+32*j; int hb=u>>6,r=(u>>1)&31,s=u&1;
                unsigned dst=base+hb*ABUF+(wm*32+r)*272+kofs+s*16;
                const __nv_bfloat16* src=(hb?al:ah)+(size_t)(wm*32+r)*128+ke+s*8;
                cp16(dst,src);
            }
            if(wm==0){
                size_t wo=((size_t)cyj*8+c)*4096;
                const __nv_bfloat16* wh=g_Wy_hi+wo; const __nv_bfloat16* wl=g_Wy_lo+wo;
#pragma unroll
                for(int j=0;j<4;++j){
                    int u=lane+32*j; int hb=u>>6,r=(u>>1)&31,s=u&1;
                    unsigned dst=base+2*ABUF+hb*WBUF+r*272+kofs+s*16;
                    const __nv_bfloat16* src=(hb?wl:wh)+(size_t)r*128+ke+s*8;
                    cp16(dst,src);
                }
            }
        };
#pragma unroll 1
        for(int it=0;it<=Sn;++it){
            if(it>=1){
                int p=it&1;
#pragma unroll
                for(int m=0;m<2;++m)
#pragma unroll
                    for(int n=0;n<4;++n)
#pragma unroll
                        for(int q=0;q<4;++q) acc[m][n][q]=0.0f;
                stage(p,0,0); cp_commit();
                stage(p,1,1); cp_commit();
                stage(p,2,2); cp_commit();
#pragma unroll 1
                for(int c=0;c<8;++c){
                    cp_wait<2>();
                    bar64(1+wk);
                    int nc=c+3;
                    if(nc<8) stage(p,nc,nc&3);
                    cp_commit();
                    compute(c);
                }
                do_red();
                __syncthreads();
                if(t<64){
#pragma unroll
                    for(int c2=0;c2<32;++c2)
                        yout[((size_t)t*Sn+(it-1))*On+cy0+c2]=plane[t*34+c2]+sby[c2];
                }
                __syncthreads();
                for(int o=t;o<64*34;o+=NTH) plane[o]=0.0f;
            }
            if(it<Sn) grid_barrier();
        }
    }
}

extern "C" void kernel_launch(void* const* d_in, const int* in_sizes, int n_in,
                              void* d_out, int out_size){
    (void)in_sizes;(void)n_in;(void)out_size;
    const float* x =(const float*)d_in[0];
    const float* h0=(const float*)d_in[1];
    const float* c0=(const float*)d_in[2];
    const float* Wf=(const float*)d_in[3];
    const float* bf=(const float*)d_in[4];
    const float* Wi=(const float*)d_in[5];
    const float* bi=(const float*)d_in[6];
    const float* Wc=(const float*)d_in[7];
    const float* bc=(const float*)d_in[8];
    const float* Wo=(const float*)d_in[9];
    const float* bo=(const float*)d_in[10];
    const float* Wy=(const float*)d_in[11];
    const float* by=(const float*)d_in[12];
    float* out=(float*)d_out;
    prep_kernel<<<4096,256>>>(Wf,Wi,Wc,Wo,Wy,x,h0);
    cudaFuncSetAttribute(lstm_mma,cudaFuncAttributeMaxDynamicSharedMemorySize,SMEMSZ);
    lstm_mma<<<NB,NTH,SMEMSZ>>>(c0,bf,bi,bc,bo,by,out);
}

// round 17
// speedup vs baseline: 1.4564x; 1.4564x over previous
#include <cuda_runtime.h>
#include <cuda_bf16.h>
#include <cstdint>
#include <cstddef>

namespace {
constexpr int Bn=64,Sn=512,Hn=1024,On=512;
constexpr int NG=128,NB=144,NTH=512;
constexpr int ABUF=17408;              // 64 rows * 272B
constexpr int WBUF=8704;               // 32 rows * 272B
constexpr int BUF=2*ABUF+2*WBUF;       // 52224
constexpr int NSTG=4;
constexpr int PLANEF=64*34;            // floats per wk-plane (2176)
// reduction planes ALIAS stage buffers 0/1 (8*2176*4 = 69632 < 2*BUF):
// written only after all chunks consumed; reclaimed by next step's staging
// after the grid barrier.
constexpr int SBYO=NSTG*BUF;           // 208896
constexpr int SMEMSZ=SBYO+128;         // 209024
}

__device__ __align__(16) __nv_bfloat16 g_Wg_hi[6291456];   // 128*12*32*128
__device__ __align__(16) __nv_bfloat16 g_Wg_lo[6291456];
__device__ __align__(16) __nv_bfloat16 g_Wy_hi[524288];    // 16*8*32*128
__device__ __align__(16) __nv_bfloat16 g_Wy_lo[524288];
__device__ __align__(16) __nv_bfloat16 g_xA_hi[16777216];  // 512*4*64*128
__device__ __align__(16) __nv_bfloat16 g_xA_lo[16777216];
__device__ __align__(16) __nv_bfloat16 g_hA_hi[131072];    // 2*8*64*128
__device__ __align__(16) __nv_bfloat16 g_hA_lo[131072];
__device__ unsigned g_count=0;
__device__ volatile unsigned g_gen=0;

static __device__ __forceinline__ void cp16(unsigned dst,const void* src){
    asm volatile("cp.async.cg.shared.global [%0], [%1], 16;"::"r"(dst),"l"(src));}
static __device__ __forceinline__ void cp_commit(){
    asm volatile("cp.async.commit_group;":::"memory");}
template<int N> static __device__ __forceinline__ void cp_wait(){
    asm volatile("cp.async.wait_group %0;"::"n"(N):"memory");}

#define LDM4(r0,r1,r2,r3,addr) \
    asm volatile("ldmatrix.sync.aligned.m8n8.x4.shared.b16 {%0,%1,%2,%3}, [%4];" \
        : "=r"(r0),"=r"(r1),"=r"(r2),"=r"(r3) : "r"(addr))

#define MMA(d,a0,a1,a2,a3,b0,b1) \
    asm volatile("mma.sync.aligned.m16n8k16.row.col.f32.bf16.bf16.f32 " \
        "{%0,%1,%2,%3},{%4,%5,%6,%7},{%8,%9},{%0,%1,%2,%3};" \
        : "+f"((d)[0]),"+f"((d)[1]),"+f"((d)[2]),"+f"((d)[3]) \
        : "r"(a0),"r"(a1),"r"(a2),"r"(a3),"r"(b0),"r"(b1))

static __device__ __forceinline__ float sigm(float v){return 1.0f/(1.0f+__expf(-v));}

static __device__ __forceinline__ void grid_barrier(){
    __syncthreads();
    if(threadIdx.x==0){
        __threadfence();
        unsigned my=g_gen;
        if(atomicAdd(&g_count,1u)==(unsigned)(NB-1)){g_count=0u;__threadfence();g_gen=my+1u;}
        else{while(g_gen==my){} __threadfence();}
    }
    __syncthreads();
}

// ---- prologue: fp32 -> bf16 hi/lo chunk layouts (row-major 128-el rows) ----
__global__ void prep_kernel(const float* __restrict__ Wf,const float* __restrict__ Wi,
                            const float* __restrict__ Wc,const float* __restrict__ Wo,
                            const float* __restrict__ Wy,const float* __restrict__ x,
                            const float* __restrict__ h0){
    const long long NWg=4LL*1024*1536, NWy=512LL*1024, Nx=64LL*512*512, Nh=64LL*1024;
    const long long TOT=NWg+NWy+Nx+Nh;
    for(long long idx=(long long)blockIdx.x*blockDim.x+threadIdx.x; idx<TOT;
        idx+=(long long)gridDim.x*blockDim.x){
        float v; long long d; __nv_bfloat16 *hi,*lo;
        if(idx<NWg){
            int g=(int)(idx/(1024*1536)); int r2=(int)(idx%(1024*1536));
            int n=r2/1536,k=r2%1536;
            const float* W=(g==0)?Wf:(g==1)?Wi:(g==2)?Wc:Wo;
            v=W[(size_t)n*1536+k];
            int blk=n>>3, rr=g*8+(n&7), ch=k>>7, kk=k&127;
            d=(((long long)blk*12+ch)*32+rr)*128+kk; hi=g_Wg_hi; lo=g_Wg_lo;
        }else if(idx<NWg+NWy){
            int i2=(int)(idx-NWg); int o=i2/1024,k=i2%1024;
            v=Wy[(size_t)o*1024+k];
            int cy=o>>5, rr=o&31, ch=k>>7, kk=k&127;
            d=(((long long)cy*8+ch)*32+rr)*128+kk; hi=g_Wy_hi; lo=g_Wy_lo;
        }else if(idx<NWg+NWy+Nx){
            long long i2=idx-NWg-NWy;
            int r=(int)(i2/(512*512)),s=(int)((i2/512)%512),k=(int)(i2%512);
            v=x[i2];
            int ch=k>>7, kk=k&127;
            d=(((long long)s*4+ch)*64+r)*128+kk; hi=g_xA_hi; lo=g_xA_lo;
        }else{
            int i2=(int)(idx-NWg-NWy-Nx); int r=i2>>10,n=i2&1023;
            v=h0[i2];
            int ch=n>>7, kk=n&127;
            d=((long long)ch*64+r)*128+kk; hi=g_hA_hi; lo=g_hA_lo;   // phase 0
        }
        __nv_bfloat16 bh=__float2bfloat16_rn(v);
        hi[d]=bh; lo[d]=__float2bfloat16_rn(v-__bfloat162float(bh));
    }
}

// ---- persistent tensor-core LSTM, 16 warps, 4-stage pipeline, lookahead 2 ----
__global__ void __launch_bounds__(NTH,1) lstm_mma(
    const float* __restrict__ c0,
    const float* __restrict__ bf_,const float* __restrict__ bi_,
    const float* __restrict__ bc_,const float* __restrict__ bo_,
    const float* __restrict__ by_,float* __restrict__ out){
    extern __shared__ char smem[];
    const unsigned sb=(unsigned)__cvta_generic_to_shared(smem);
    const int blk=blockIdx.x,t=threadIdx.x,wrp=t>>5,lane=t&31;
    float* yout=out;
    float* hout=out+(size_t)Bn*Sn*On;
    float* cout=hout+(size_t)Bn*Hn;
    float* plane=(float*)smem;            // aliases stage buffers 0/1

    const int wm=wrp&1, wk=wrp>>1;        // M-half, k-slice
    const unsigned kofs=wk*32;            // bytes
    const int arow=lane&15, aseg=(lane>>4)*16;
    const int brow=((lane>>4)<<3)+(lane&7), bofs=((lane>>3)&1)*16;

    float acc[2][4][4];

    auto compute=[&](int c){
        unsigned Ab=sb+(unsigned)(c&3)*BUF, Wb=Ab+2*ABUF;
        unsigned bh[8],bl[8];
        unsigned b0=Wb+brow*272+kofs+bofs;
        LDM4(bh[0],bh[1],bh[2],bh[3],b0);
        LDM4(bh[4],bh[5],bh[6],bh[7],b0+16*272);
        LDM4(bl[0],bl[1],bl[2],bl[3],b0+WBUF);
        LDM4(bl[4],bl[5],bl[6],bl[7],b0+WBUF+16*272);
        unsigned a0=Ab+(wm*32+arow)*272+kofs+aseg;
#pragma unroll
        for(int m=0;m<2;++m){
            unsigned ah0,ah1,ah2,ah3,al0,al1,al2,al3;
            LDM4(ah0,ah1,ah2,ah3,a0+m*4352);
            LDM4(al0,al1,al2,al3,a0+m*4352+ABUF);
#pragma unroll
            for(int n=0;n<4;++n){
                MMA(acc[m][n],ah0,ah1,ah2,ah3,bh[2*n],bh[2*n+1]);
                MMA(acc[m][n],al0,al1,al2,al3,bh[2*n],bh[2*n+1]);
                MMA(acc[m][n],ah0,ah1,ah2,ah3,bl[2*n],bl[2*n+1]);
            }
        }
    };
    // per-warp plane write: plane[wk], rows wm*32.. (disjoint across pair)
    auto put_plane=[&](){
        float* rp=plane+wk*PLANEF;
        int g=lane>>2,t2=lane&3;
#pragma unroll
        for(int m=0;m<2;++m)
#pragma unroll
            for(int h=0;h<2;++h){
                int r=wm*32+16*m+8*h+g;
#pragma unroll
                for(int n=0;n<4;++n)
                    *(float2*)&rp[r*34+8*n+2*t2]=
                        make_float2(acc[m][n][2*h],acc[m][n][2*h+1]);
            }
    };
    auto reduce8=[&](){
#pragma unroll 1
        for(int o=t;o<PLANEF;o+=NTH){
            float s=0.0f;
#pragma unroll
            for(int p2=0;p2<8;++p2) s+=plane[p2*PLANEF+o];
            plane[o]=s;
        }
    };

    if(blk<NG){
        const int n0=blk*8;
        float cell[8],vbf[8],vbi[8],vbc[8],vbo[8];
        if(t<64){
#pragma unroll
            for(int d=0;d<8;++d){
                cell[d]=c0[(size_t)t*Hn+n0+d];
                vbf[d]=bf_[n0+d];vbi[d]=bi_[n0+d];vbc[d]=bc_[n0+d];vbo[d]=bo_[n0+d];
            }
        }
        auto stage=[&](int it2,int c){
            const __nv_bfloat16 *ah,*al;
            if(c<4){ size_t o=((size_t)it2*4+c)*8192; ah=g_xA_hi+o; al=g_xA_lo+o; }
            else   { size_t o=((size_t)(it2&1)*8+(c-4))*8192; ah=g_hA_hi+o; al=g_hA_lo+o; }
            size_t wo=((size_t)blk*12+c)*4096;
            const __nv_bfloat16* wh=g_Wg_hi+wo; const __nv_bfloat16* wl=g_Wg_lo+wo;
            unsigned base=sb+(unsigned)(c&3)*BUF;
#pragma unroll 1
            for(int i=t;i<3072;i+=NTH){
                unsigned dst; const __nv_bfloat16* src;
                if(i<2048){ int hb=i>>10,row=(i>>4)&63,seg=i&15;
                    dst=base+hb*ABUF+row*272+seg*16; src=(hb?al:ah)+row*128+seg*8;
                }else{ int j=i-2048; int hb=j>>9,row=(j>>4)&31,seg=j&15;
                    dst=base+2*ABUF+hb*WBUF+row*272+seg*16; src=(hb?wl:wh)+row*128+seg*8; }
                cp16(dst,src);
            }
        };

#pragma unroll 1
        for(int it=0;it<Sn;++it){
#pragma unroll
            for(int m=0;m<2;++m)
#pragma unroll
                for(int n=0;n<4;++n)
#pragma unroll
                    for(int q=0;q<4;++q) acc[m][n][q]=0.0f;

            stage(it,0); cp_commit();
            stage(it,1); cp_commit();
            stage(it,2); cp_commit();
#pragma unroll 1
            for(int c=0;c<12;++c){
                if(c<10) cp_wait<2>(); else if(c==10) cp_wait<1>(); else cp_wait<0>();
                __syncthreads();
                if(c+3<12){ stage(it,c+3); cp_commit(); }
                compute(c);
            }
            put_plane();
            __syncthreads();
            reduce8();
            __syncthreads();
            if(t<64){
                float P[32];
#pragma unroll
                for(int c2=0;c2<32;++c2) P[c2]=plane[t*34+c2];
                unsigned short hs[8],ls[8];
#pragma unroll
                for(int d=0;d<8;++d){
                    float f=sigm(P[d]+vbf[d]);
                    float ii=sigm(P[8+d]+vbi[d]);
                    float g=tanhf(P[16+d]+vbc[d]);
                    float o=sigm(P[24+d]+vbo[d]);
                    cell[d]=f*cell[d]+ii*g;
                    float hh=o*tanhf(cell[d]);
                    __nv_bfloat16 bh2=__float2bfloat16_rn(hh);
                    __nv_bfloat16 bl2=__float2bfloat16_rn(hh-__bfloat162float(bh2));
                    hs[d]=__bfloat16_as_ushort(bh2); ls[d]=__bfloat16_as_ushort(bl2);
                    if(it==Sn-1){ hout[(size_t)t*Hn+n0+d]=hh; cout[(size_t)t*Hn+n0+d]=cell[d]; }
                }
                int p1=(it+1)&1,hc=n0>>7,ko=n0&127;
                size_t eo=(((size_t)p1*8+hc)*64+t)*128+ko;
                uint4 vh=make_uint4(hs[0]|((unsigned)hs[1]<<16),hs[2]|((unsigned)hs[3]<<16),
                                    hs[4]|((unsigned)hs[5]<<16),hs[6]|((unsigned)hs[7]<<16));
                uint4 vl=make_uint4(ls[0]|((unsigned)ls[1]<<16),ls[2]|((unsigned)ls[3]<<16),
                                    ls[4]|((unsigned)ls[5]<<16),ls[6]|((unsigned)ls[7]<<16));
                *(uint4*)((char*)g_hA_hi+eo*2)=vh;
                *(uint4*)((char*)g_hA_lo+eo*2)=vl;
            }
            grid_barrier();
        }
    }else{
        const int cyj=blk-NG, cy0=cyj*32;
        float* sby=(float*)(smem+SBYO);
        if(t<32) sby[t]=by_[cy0+t];
        __syncthreads();
        auto stage=[&](int p,int c){
            size_t o=((size_t)p*8+c)*8192;
            const __nv_bfloat16* ah=g_hA_hi+o; const __nv_bfloat16* al=g_hA_lo+o;
            size_t wo=((size_t)cyj*8+c)*4096;
            const __nv_bfloat16* wh=g_Wy_hi+wo; const __nv_bfloat16* wl=g_Wy_lo+wo;
            unsigned base=sb+(unsigned)(c&3)*BUF;
#pragma unroll 1
            for(int i=t;i<3072;i+=NTH){
                unsigned dst; const __nv_bfloat16* src;
                if(i<2048){ int hb=i>>10,row=(i>>4)&63,seg=i&15;
                    dst=base+hb*ABUF+row*272+seg*16; src=(hb?al:ah)+row*128+seg*8;
                }else{ int j=i-2048; int hb=j>>9,row=(j>>4)&31,seg=j&15;
                    dst=base+2*ABUF+hb*WBUF+row*272+seg*16; src=(hb?wl:wh)+row*128+seg*8; }
                cp16(dst,src);
            }
        };
#pragma unroll 1
        for(int it=0;it<=Sn;++it){
            if(it>=1){
                int p=it&1;
#pragma unroll
                for(int m=0;m<2;++m)
#pragma unroll
                    for(int n=0;n<4;++n)
#pragma unroll
                        for(int q=0;q<4;++q) acc[m][n][q]=0.0f;
                stage(p,0); cp_commit();
                stage(p,1); cp_commit();
                stage(p,2); cp_commit();
#pragma unroll 1
                for(int c=0;c<8;++c){
                    if(c<6) cp_wait<2>(); else if(c==6) cp_wait<1>(); else cp_wait<0>();
                    __syncthreads();
                    if(c+3<8){ stage(p,c+3); cp_commit(); }
                    compute(c);
                }
                put_plane();
                __syncthreads();
                reduce8();
                __syncthreads();
                if(t<64){
#pragma unroll
                    for(int c2=0;c2<32;++c2)
                        yout[((size_t)t*Sn+(it-1))*On+cy0+c2]=plane[t*34+c2]+sby[c2];
                }
            }
            if(it<Sn) grid_barrier();
        }
    }
}

extern "C" void kernel_launch(void* const* d_in, const int* in_sizes, int n_in,
                              void* d_out, int out_size){
    (void)in_sizes;(void)n_in;(void)out_size;
    const float* x =(const float*)d_in[0];
    const float* h0=(const float*)d_in[1];
    const float* c0=(const float*)d_in[2];
    const float* Wf=(const float*)d_in[3];
    const float* bf=(const float*)d_in[4];
    const float* Wi=(const float*)d_in[5];
    const float* bi=(const float*)d_in[6];
    const float* Wc=(const float*)d_in[7];
    const float* bc=(const float*)d_in[8];
    const float* Wo=(const float*)d_in[9];
    const float* bo=(const float*)d_in[10];
    const float* Wy=(const float*)d_in[11];
    const float* by=(const float*)d_in[12];
    float* out=(float*)d_out;
    prep_kernel<<<4096,256>>>(Wf,Wi,Wc,Wo,Wy,x,h0);
    cudaFuncSetAttribute(lstm_mma,cudaFuncAttributeMaxDynamicSharedMemorySize,SMEMSZ);
    lstm_mma<<<NB,NTH,SMEMSZ>>>(c0,bf,bi,bc,bo,by,out);
}